// round 1
// baseline (speedup 1.0000x reference)
#include <cuda_runtime.h>
#include <cstdint>
#include <math.h>

#define N_ATOMS  10000
#define N_STRUCT 100
#define NPSEUDO  4
#define NSPECIES 4
#define QDIM     32
#define NFEAT    4096
#define HIDDEN   256

#define BM 128
#define BN 128
#define BK 16
#define ASTRIDE 20   // BK + 4 pad -> conflict-free A fragment loads
#define BSTRIDE 136  // BN + 8 pad -> conflict-free B fragment loads

// ---------------- scratch (static device globals; no allocation) ----------------
__device__ float g_features[(size_t)N_ATOMS * NFEAT];                 // 163.8 MB
__device__ float g_h1[(size_t)NPSEUDO * N_ATOMS * HIDDEN];            // 41 MB
__device__ float g_h2[(size_t)NPSEUDO * N_ATOMS * HIDDEN];            // 41 MB
__device__ float g_W0t[(size_t)NPSEUDO * NFEAT * HIDDEN];             // 16.8 MB
__device__ float g_W1t[(size_t)NPSEUDO * HIDDEN * HIDDEN];            // 1 MB

__device__ __forceinline__ float to_tf32(float x) {
    uint32_t u;
    asm("cvt.rna.tf32.f32 %0, %1;" : "=r"(u) : "f"(x));
    return __uint_as_float(u);
}

__device__ __forceinline__ float silu(float x) {
    return x / (1.0f + expf(-x));
}

// ---------------- weight conversion (fp32 -> tf32-rounded fp32) ----------------
__global__ void convert_weights_kernel(const float* __restrict__ W0,
                                       const float* __restrict__ W1) {
    size_t i = (size_t)blockIdx.x * 256 + threadIdx.x;
    const size_t n0 = (size_t)NPSEUDO * NFEAT * HIDDEN;
    const size_t n1 = (size_t)NPSEUDO * HIDDEN * HIDDEN;
    if (i < n0) g_W0t[i] = to_tf32(W0[i]);
    if (i < n1) g_W1t[i] = to_tf32(W1[i]);
}

// ---------------- power spectrum features ----------------
// features[a, l*1024 + q*32 + r] = (1/sqrt(2l+1)) * sum_m c_l[a,m,q]*c_l[a,m,r]
__global__ void features_kernel(const float* __restrict__ c0,
                                const float* __restrict__ c1,
                                const float* __restrict__ c2,
                                const float* __restrict__ c3) {
    __shared__ float sc[512];  // (1+3+5+7)*32 floats
    const int a = blockIdx.x;
    const int t = threadIdx.x;

    #pragma unroll
    for (int j = 0; j < 2; j++) {
        int idx = t + 256 * j;
        float v;
        if (idx < 32)        v = c0[(size_t)a * 32  + idx];
        else if (idx < 128)  v = c1[(size_t)a * 96  + (idx - 32)];
        else if (idx < 288)  v = c2[(size_t)a * 160 + (idx - 128)];
        else                 v = c3[(size_t)a * 224 + (idx - 288)];
        sc[idx] = v;
    }
    __syncthreads();

    const int   loff[4] = {0, 32, 128, 288};
    const float cg[4]   = {1.0f, 0.57735026919f, 0.44721359550f, 0.37796447301f};
    const size_t base = (size_t)a * NFEAT;

    #pragma unroll
    for (int j = 0; j < 16; j++) {
        int f   = t + 256 * j;
        int l   = f >> 10;
        int rem = f & 1023;
        int q   = rem >> 5;
        int r   = rem & 31;
        const float* cl = sc + loff[l];
        int nm = 2 * l + 1;
        float s = 0.0f;
        for (int m = 0; m < nm; m++)
            s += cl[m * 32 + q] * cl[m * 32 + r];
        g_features[base + f] = to_tf32(cg[l] * s);
    }
}

// ---------------- tf32 mma helper ----------------
__device__ __forceinline__ void mma_tf32(float c[4], const uint32_t a[4], const uint32_t b[2]) {
    asm volatile(
        "mma.sync.aligned.m16n8k8.row.col.f32.tf32.tf32.f32 "
        "{%0,%1,%2,%3}, {%4,%5,%6,%7}, {%8,%9}, {%0,%1,%2,%3};\n"
        : "+f"(c[0]), "+f"(c[1]), "+f"(c[2]), "+f"(c[3])
        : "r"(a[0]), "r"(a[1]), "r"(a[2]), "r"(a[3]), "r"(b[0]), "r"(b[1]));
}

// ---------------- GEMM: C[p] = epilogue(A[p] @ B[p]) ----------------
// MODE 0: A=features [A,4096], B=W0t[p] [4096,256], C=h1[p]; epi: silu(pw * acc)
// MODE 1: A=h1[p]    [A, 256], B=W1t[p] [ 256,256], C=h2[p]; epi: silu(acc)
template<int MODE, int KTILES>
__global__ void __launch_bounds__(256, 2)
gemm_tf32_kernel(const float* __restrict__ combW, const int* __restrict__ species) {
    __shared__ float As[2][BM * ASTRIDE];
    __shared__ float Bs[2][BK * BSTRIDE];

    const int p  = blockIdx.z;
    const int m0 = blockIdx.x * BM;
    const int n0 = blockIdx.y * BN;

    const float* A; const float* B; float* C; int ldA;
    if (MODE == 0) {
        A = g_features;
        B = g_W0t + (size_t)p * NFEAT * HIDDEN;
        C = g_h1  + (size_t)p * N_ATOMS * HIDDEN;
        ldA = NFEAT;
    } else {
        A = g_h1  + (size_t)p * N_ATOMS * HIDDEN;
        B = g_W1t + (size_t)p * HIDDEN * HIDDEN;
        C = g_h2  + (size_t)p * N_ATOMS * HIDDEN;
        ldA = HIDDEN;
    }

    const int tid  = threadIdx.x;
    const int warp = tid >> 5;
    const int lane = tid & 31;
    const int grp  = lane >> 2;   // 0..7
    const int tig  = lane & 3;    // 0..3
    const int wm   = (warp & 3) * 32;   // 4 warps along M -> 128
    const int wn   = (warp >> 2) * 64;  // 2 warps along N -> 128

    float acc[2][8][4];
    #pragma unroll
    for (int mt = 0; mt < 2; mt++)
        #pragma unroll
        for (int nt = 0; nt < 8; nt++)
            #pragma unroll
            for (int i = 0; i < 4; i++)
                acc[mt][nt][i] = 0.0f;

    const uint32_t sA = (uint32_t)__cvta_generic_to_shared(&As[0][0]);
    const uint32_t sB = (uint32_t)__cvta_generic_to_shared(&Bs[0][0]);

    // tile loader via cp.async (zero-fill for OOB atom rows)
    auto load_tile = [&](int kb, int buf) {
        #pragma unroll
        for (int j = 0; j < 2; j++) {
            int f4 = tid + 256 * j;          // 512 float4 for 128x16 A tile
            int m  = f4 >> 2;
            int kq = (f4 & 3) * 4;
            int row = m0 + m;
            const float* src = A + (size_t)row * ldA + kb * BK + kq;
            uint32_t dst = sA + (uint32_t)(buf * BM * ASTRIDE + m * ASTRIDE + kq) * 4u;
            int sz = (row < N_ATOMS) ? 16 : 0;
            asm volatile("cp.async.ca.shared.global [%0], [%1], 16, %2;\n"
                         :: "r"(dst), "l"(src), "r"(sz));
        }
        #pragma unroll
        for (int j = 0; j < 2; j++) {
            int f4 = tid + 256 * j;          // 512 float4 for 16x128 B tile
            int k  = f4 >> 5;
            int nq = (f4 & 31) * 4;
            const float* src = B + (size_t)(kb * BK + k) * HIDDEN + n0 + nq;
            uint32_t dst = sB + (uint32_t)(buf * BK * BSTRIDE + k * BSTRIDE + nq) * 4u;
            asm volatile("cp.async.ca.shared.global [%0], [%1], 16;\n"
                         :: "r"(dst), "l"(src));
        }
        asm volatile("cp.async.commit_group;\n");
    };

    load_tile(0, 0);
    int buf = 0;

    for (int kb = 0; kb < KTILES; kb++) {
        if (kb + 1 < KTILES) {
            load_tile(kb + 1, buf ^ 1);
            asm volatile("cp.async.wait_group 1;\n");
        } else {
            asm volatile("cp.async.wait_group 0;\n");
        }
        __syncthreads();

        const float* Ab = &As[buf][0];
        const float* Bb = &Bs[buf][0];
        #pragma unroll
        for (int ks = 0; ks < 2; ks++) {
            const int k = ks * 8;
            uint32_t af[2][4];
            uint32_t bf[8][2];
            #pragma unroll
            for (int mt = 0; mt < 2; mt++) {
                int r0 = wm + mt * 16 + grp;
                af[mt][0] = __float_as_uint(Ab[(r0    ) * ASTRIDE + k + tig    ]);
                af[mt][1] = __float_as_uint(Ab[(r0 + 8) * ASTRIDE + k + tig    ]);
                af[mt][2] = __float_as_uint(Ab[(r0    ) * ASTRIDE + k + tig + 4]);
                af[mt][3] = __float_as_uint(Ab[(r0 + 8) * ASTRIDE + k + tig + 4]);
            }
            #pragma unroll
            for (int nt = 0; nt < 8; nt++) {
                int c = wn + nt * 8 + grp;
                bf[nt][0] = __float_as_uint(Bb[(k + tig    ) * BSTRIDE + c]);
                bf[nt][1] = __float_as_uint(Bb[(k + tig + 4) * BSTRIDE + c]);
            }
            #pragma unroll
            for (int mt = 0; mt < 2; mt++)
                #pragma unroll
                for (int nt = 0; nt < 8; nt++)
                    mma_tf32(acc[mt][nt], af[mt], bf[nt]);
        }
        __syncthreads();
        buf ^= 1;
    }

    // epilogue
    #pragma unroll
    for (int mt = 0; mt < 2; mt++) {
        int r0 = m0 + wm + mt * 16 + grp;
        int r1 = r0 + 8;
        float pw0 = 0.0f, pw1 = 0.0f;
        if (MODE == 0) {
            if (r0 < N_ATOMS) pw0 = combW[p * NSPECIES + species[r0]];
            if (r1 < N_ATOMS) pw1 = combW[p * NSPECIES + species[r1]];
        }
        #pragma unroll
        for (int nt = 0; nt < 8; nt++) {
            int c = n0 + wn + nt * 8 + tig * 2;
            if (r0 < N_ATOMS) {
                float x0 = acc[mt][nt][0], x1 = acc[mt][nt][1];
                if (MODE == 0) { x0 *= pw0; x1 *= pw0; }
                C[(size_t)r0 * HIDDEN + c    ] = silu(x0);
                C[(size_t)r0 * HIDDEN + c + 1] = silu(x1);
            }
            if (r1 < N_ATOMS) {
                float x2 = acc[mt][nt][2], x3 = acc[mt][nt][3];
                if (MODE == 0) { x2 *= pw1; x3 *= pw1; }
                C[(size_t)r1 * HIDDEN + c    ] = silu(x2);
                C[(size_t)r1 * HIDDEN + c + 1] = silu(x3);
            }
        }
    }
}

// ---------------- final dot + segment sum ----------------
__global__ void zero_out_kernel(float* out) {
    if (threadIdx.x < N_STRUCT) out[threadIdx.x] = 0.0f;
}

__global__ void reduce_kernel(const float* __restrict__ W2,
                              const int* __restrict__ sid,
                              float* __restrict__ out) {
    const int a = blockIdx.x;
    const int t = threadIdx.x;
    float v = 0.0f;
    #pragma unroll
    for (int p = 0; p < NPSEUDO; p++)
        v += g_h2[((size_t)p * N_ATOMS + a) * HIDDEN + t] * W2[p * HIDDEN + t];

    __shared__ float red[8];
    #pragma unroll
    for (int o = 16; o > 0; o >>= 1) v += __shfl_down_sync(0xffffffffu, v, o);
    if ((t & 31) == 0) red[t >> 5] = v;
    __syncthreads();
    if (t < 8) {
        float s = red[t];
        #pragma unroll
        for (int o = 4; o > 0; o >>= 1) s += __shfl_down_sync(0xffu, s, o);
        if (t == 0) atomicAdd(&out[sid[a]], s);
    }
}

// ---------------- launch ----------------
extern "C" void kernel_launch(void* const* d_in, const int* in_sizes, int n_in,
                              void* d_out, int out_size) {
    const float* c0      = (const float*)d_in[0];
    const float* c1      = (const float*)d_in[1];
    const float* c2      = (const float*)d_in[2];
    const float* c3      = (const float*)d_in[3];
    const int*   species = (const int*)d_in[4];
    const int*   sid     = (const int*)d_in[5];
    const float* combW   = (const float*)d_in[6];
    const float* W0      = (const float*)d_in[7];
    const float* W1      = (const float*)d_in[8];
    const float* W2      = (const float*)d_in[9];
    float* out = (float*)d_out;

    const int n_conv = NPSEUDO * NFEAT * HIDDEN;  // covers W1 too (smaller)
    convert_weights_kernel<<<(n_conv + 255) / 256, 256>>>(W0, W1);

    features_kernel<<<N_ATOMS, 256>>>(c0, c1, c2, c3);

    dim3 grid((N_ATOMS + BM - 1) / BM, HIDDEN / BN, NPSEUDO);
    gemm_tf32_kernel<0, NFEAT / BK><<<grid, 256>>>(combW, species);
    gemm_tf32_kernel<1, HIDDEN / BK><<<grid, 256>>>(combW, species);

    zero_out_kernel<<<1, 128>>>(out);
    reduce_kernel<<<N_ATOMS, 256>>>(W2, sid, out);
}

// round 3
// speedup vs baseline: 1.4796x; 1.4796x over previous
#include <cuda_runtime.h>
#include <cstdint>
#include <math.h>

#define N_ATOMS  10000
#define N_STRUCT 100
#define NPSEUDO  4
#define NSPECIES 4
#define NFEAT    4096
#define HIDDEN   256
#define NPACK    2112   // 4 * 528 (triangular q<=r packing of 32x32 per l)

// ---------------- scratch (static device globals; no allocation) ----------------
__device__ float g_feat[(size_t)N_ATOMS * NPACK];                     // 84.5 MB (packed, tf32)
__device__ float g_h1[(size_t)NPSEUDO * N_ATOMS * HIDDEN];            // 41 MB
__device__ float g_h2[(size_t)NPSEUDO * N_ATOMS * HIDDEN];            // 41 MB
__device__ float g_W0s[(size_t)NPSEUDO * NPACK * HIDDEN];             // 8.7 MB [p][lin][h] symmetrized
__device__ float g_W1t[(size_t)NPSEUDO * HIDDEN * HIDDEN];            // 1 MB   [p][k][n]

__device__ __forceinline__ float to_tf32(float x) {
    uint32_t u;
    asm("cvt.rna.tf32.f32 %0, %1;" : "=r"(u) : "f"(x));
    return __uint_as_float(u);
}
__device__ __forceinline__ float silu(float x) { return x / (1.0f + expf(-x)); }

__device__ __forceinline__ uint32_t smem_u32(const void* p) {
    uint32_t a;
    asm("{ .reg .u64 t; cvta.to.shared.u64 t, %1; cvt.u32.u64 %0, t; }" : "=r"(a) : "l"(p));
    return a;
}

// triangular decode: t2 in [0,528) -> (q, r), q<=r<32.  S(q) = q*(65-q)/2
__device__ __forceinline__ void tri_decode(int t2, int& q, int& r) {
    q = (int)((65.0f - sqrtf(4225.0f - 8.0f * (float)t2)) * 0.5f);
    if (q < 0) q = 0;
    while (q * (65 - q) / 2 > t2) q--;
    while ((q + 1) * (64 - q) / 2 <= t2) q++;
    r = q + (t2 - q * (65 - q) / 2);
}

// ---------------- symmetrized weight conversion ----------------
// g_W0s[p][lin][h] = tf32( W0[p][f(q,r)][h] + (q<r ? W0[p][f(r,q)][h] : 0) )
__global__ void convert_w0_kernel(const float* __restrict__ W0) {
    const int h   = threadIdx.x;             // 256
    const int lin = blockIdx.x;              // 2112
    const int p   = blockIdx.y;              // 4
    const int l   = lin / 528;
    const int t2  = lin - l * 528;
    int q, r;
    tri_decode(t2, q, r);
    const size_t base = (size_t)p * NFEAT * HIDDEN;
    float v = W0[base + (size_t)(l * 1024 + q * 32 + r) * HIDDEN + h];
    if (q != r) v += W0[base + (size_t)(l * 1024 + r * 32 + q) * HIDDEN + h];
    g_W0s[((size_t)p * NPACK + lin) * HIDDEN + h] = to_tf32(v);
}

__global__ void convert_w1_kernel(const float* __restrict__ W1) {
    size_t i = (size_t)blockIdx.x * 256 + threadIdx.x;
    const size_t n1 = (size_t)NPSEUDO * HIDDEN * HIDDEN;
    if (i < n1) g_W1t[i] = to_tf32(W1[i]);
}

// ---------------- packed power spectrum features ----------------
__global__ void features_kernel(const float* __restrict__ c0,
                                const float* __restrict__ c1,
                                const float* __restrict__ c2,
                                const float* __restrict__ c3) {
    __shared__ float sc[512];
    const int a = blockIdx.x;
    const int t = threadIdx.x;
    #pragma unroll
    for (int j = 0; j < 2; j++) {
        int idx = t + 256 * j;
        float v;
        if (idx < 32)        v = c0[(size_t)a * 32  + idx];
        else if (idx < 128)  v = c1[(size_t)a * 96  + (idx - 32)];
        else if (idx < 288)  v = c2[(size_t)a * 160 + (idx - 128)];
        else                 v = c3[(size_t)a * 224 + (idx - 288)];
        sc[idx] = v;
    }
    __syncthreads();
    const int   loff[4] = {0, 32, 128, 288};
    const float cg[4]   = {1.0f, 0.57735026919f, 0.44721359550f, 0.37796447301f};
    const size_t base = (size_t)a * NPACK;
    #pragma unroll
    for (int j = 0; j < 9; j++) {
        int lin = t + 256 * j;
        if (lin < NPACK) {
            int l  = lin / 528;
            int t2 = lin - l * 528;
            int q, r;
            tri_decode(t2, q, r);
            const float* cl = sc + loff[l];
            int nm = 2 * l + 1;
            float s = 0.0f;
            for (int m = 0; m < nm; m++) s += cl[m * 32 + q] * cl[m * 32 + r];
            g_feat[base + lin] = to_tf32(cg[l] * s);
        }
    }
}

// ---------------- tf32 mma helper ----------------
__device__ __forceinline__ void mma_tf32(float c[4], const uint32_t a[4], const uint32_t b[2]) {
    asm volatile(
        "mma.sync.aligned.m16n8k8.row.col.f32.tf32.tf32.f32 "
        "{%0,%1,%2,%3}, {%4,%5,%6,%7}, {%8,%9}, {%0,%1,%2,%3};\n"
        : "+f"(c[0]), "+f"(c[1]), "+f"(c[2]), "+f"(c[3])
        : "r"(a[0]), "r"(a[1]), "r"(a[2]), "r"(a[3]), "r"(b[0]), "r"(b[1]));
}

// ================= GEMM0: h1[p] = silu(pw * feat_packed @ W0s[p]) =================
// BM=128 atoms, BN=256 (full hidden), BK=16, K=2112 (132 tiles), 3-stage cp.async.
// 8 warps: 4 along M (32 rows each) x 2 along N (128 cols each).
#define G0_BK      16
#define G0_KT      (NPACK / G0_BK)      // 132
#define G0_ASTR    20                   // words; conflict-free A frags
#define G0_BSTR    264                  // words; 264 mod 32 == 8 -> conflict-free B frags
#define G0_ASZ     (128 * G0_ASTR * 4)  // 10240 B
#define G0_BSZ     (G0_BK * G0_BSTR * 4)// 16896 B
#define G0_STAGE   (G0_ASZ + G0_BSZ)
#define G0_STAGES  3
#define G0_DSMEM   (G0_STAGES * G0_STAGE)

__global__ void __launch_bounds__(256, 1)
gemm0_kernel(const float* __restrict__ combW, const int* __restrict__ species) {
    extern __shared__ float dsm[];

    const int p  = blockIdx.x;
    const int m0 = blockIdx.y * 128;

    const float* A = g_feat;
    const float* B = g_W0s + (size_t)p * NPACK * HIDDEN;
    float*       C = g_h1  + (size_t)p * N_ATOMS * HIDDEN;

    const int tid  = threadIdx.x;
    const int warp = tid >> 5;
    const int lane = tid & 31;
    const int grp  = lane >> 2;
    const int tig  = lane & 3;
    const int wm   = (warp & 3) * 32;    // 4 warps along M
    const int wn   = (warp >> 2) * 128;  // 2 warps along N

    float acc[2][16][4];
    #pragma unroll
    for (int mt = 0; mt < 2; mt++)
        #pragma unroll
        for (int nt = 0; nt < 16; nt++)
            #pragma unroll
            for (int i = 0; i < 4; i++) acc[mt][nt][i] = 0.0f;

    const uint32_t sbase = smem_u32(dsm);

    auto load_tile = [&](int kb, int b) {
        const uint32_t sA = sbase + (uint32_t)b * G0_STAGE;
        const uint32_t sB = sA + G0_ASZ;
        // A tile: 128x16 floats = 512 float4
        #pragma unroll
        for (int j = 0; j < 2; j++) {
            int f4 = tid + 256 * j;
            int m  = f4 >> 2;
            int kq = (f4 & 3) * 4;
            int row = m0 + m;
            const float* src = A + (size_t)row * NPACK + kb * G0_BK + kq;
            uint32_t dst = sA + (uint32_t)(m * G0_ASTR + kq) * 4u;
            int sz = (row < N_ATOMS) ? 16 : 0;
            asm volatile("cp.async.ca.shared.global [%0], [%1], 16, %2;\n"
                         :: "r"(dst), "l"(src), "r"(sz));
        }
        // B tile: 16x256 floats = 1024 float4
        #pragma unroll
        for (int j = 0; j < 4; j++) {
            int f4 = tid + 256 * j;
            int k  = f4 >> 6;
            int nq = (f4 & 63) * 4;
            const float* src = B + (size_t)(kb * G0_BK + k) * HIDDEN + nq;
            uint32_t dst = sB + (uint32_t)(k * G0_BSTR + nq) * 4u;
            asm volatile("cp.async.ca.shared.global [%0], [%1], 16;\n"
                         :: "r"(dst), "l"(src));
        }
        asm volatile("cp.async.commit_group;\n");
    };

    load_tile(0, 0);
    load_tile(1, 1);

    for (int kb = 0; kb < G0_KT; kb++) {
        const int b = kb % G0_STAGES;
        if (kb + 2 < G0_KT) {
            load_tile(kb + 2, (kb + 2) % G0_STAGES);
            asm volatile("cp.async.wait_group 2;\n");
        } else if (kb + 1 < G0_KT) {
            asm volatile("cp.async.wait_group 1;\n");
        } else {
            asm volatile("cp.async.wait_group 0;\n");
        }
        __syncthreads();

        const float* Ab = dsm + (size_t)b * (G0_STAGE / 4);
        const float* Bb = Ab + G0_ASZ / 4;
        #pragma unroll
        for (int ks = 0; ks < 2; ks++) {
            const int k = ks * 8;
            uint32_t af[2][4];
            uint32_t bf[16][2];
            #pragma unroll
            for (int mt = 0; mt < 2; mt++) {
                int r0 = wm + mt * 16 + grp;
                af[mt][0] = __float_as_uint(Ab[(r0    ) * G0_ASTR + k + tig    ]);
                af[mt][1] = __float_as_uint(Ab[(r0 + 8) * G0_ASTR + k + tig    ]);
                af[mt][2] = __float_as_uint(Ab[(r0    ) * G0_ASTR + k + tig + 4]);
                af[mt][3] = __float_as_uint(Ab[(r0 + 8) * G0_ASTR + k + tig + 4]);
            }
            #pragma unroll
            for (int nt = 0; nt < 16; nt++) {
                int c = wn + nt * 8 + grp;
                bf[nt][0] = __float_as_uint(Bb[(k + tig    ) * G0_BSTR + c]);
                bf[nt][1] = __float_as_uint(Bb[(k + tig + 4) * G0_BSTR + c]);
            }
            #pragma unroll
            for (int mt = 0; mt < 2; mt++)
                #pragma unroll
                for (int nt = 0; nt < 16; nt++)
                    mma_tf32(acc[mt][nt], af[mt], bf[nt]);
        }
        __syncthreads();
    }

    // epilogue: silu(pw * acc)
    #pragma unroll
    for (int mt = 0; mt < 2; mt++) {
        int r0 = m0 + wm + mt * 16 + grp;
        int r1 = r0 + 8;
        float pw0 = 0.0f, pw1 = 0.0f;
        if (r0 < N_ATOMS) pw0 = combW[p * NSPECIES + species[r0]];
        if (r1 < N_ATOMS) pw1 = combW[p * NSPECIES + species[r1]];
        #pragma unroll
        for (int nt = 0; nt < 16; nt++) {
            int c = wn + nt * 8 + tig * 2;
            if (r0 < N_ATOMS) {
                C[(size_t)r0 * HIDDEN + c    ] = silu(acc[mt][nt][0] * pw0);
                C[(size_t)r0 * HIDDEN + c + 1] = silu(acc[mt][nt][1] * pw0);
            }
            if (r1 < N_ATOMS) {
                C[(size_t)r1 * HIDDEN + c    ] = silu(acc[mt][nt][2] * pw1);
                C[(size_t)r1 * HIDDEN + c + 1] = silu(acc[mt][nt][3] * pw1);
            }
        }
    }
}

// ================= GEMM1 (verified R1 config): h2[p] = silu(h1[p] @ W1t[p]) =================
#define BM 128
#define BN 128
#define BK 16
#define ASTRIDE 20
#define BSTRIDE 136

__global__ void __launch_bounds__(256, 2)
gemm1_kernel() {
    __shared__ float As[2][BM * ASTRIDE];
    __shared__ float Bs[2][BK * BSTRIDE];

    const int p  = blockIdx.z;
    const int m0 = blockIdx.x * BM;
    const int n0 = blockIdx.y * BN;

    const float* A = g_h1  + (size_t)p * N_ATOMS * HIDDEN;
    const float* B = g_W1t + (size_t)p * HIDDEN * HIDDEN;
    float*       C = g_h2  + (size_t)p * N_ATOMS * HIDDEN;

    const int tid  = threadIdx.x;
    const int warp = tid >> 5;
    const int lane = tid & 31;
    const int grp  = lane >> 2;
    const int tig  = lane & 3;
    const int wm   = (warp & 3) * 32;
    const int wn   = (warp >> 2) * 64;

    float acc[2][8][4];
    #pragma unroll
    for (int mt = 0; mt < 2; mt++)
        #pragma unroll
        for (int nt = 0; nt < 8; nt++)
            #pragma unroll
            for (int i = 0; i < 4; i++) acc[mt][nt][i] = 0.0f;

    const uint32_t sA = smem_u32(&As[0][0]);
    const uint32_t sB = smem_u32(&Bs[0][0]);

    auto load_tile = [&](int kb, int buf) {
        #pragma unroll
        for (int j = 0; j < 2; j++) {
            int f4 = tid + 256 * j;
            int m  = f4 >> 2;
            int kq = (f4 & 3) * 4;
            int row = m0 + m;
            const float* src = A + (size_t)row * HIDDEN + kb * BK + kq;
            uint32_t dst = sA + (uint32_t)(buf * BM * ASTRIDE + m * ASTRIDE + kq) * 4u;
            int sz = (row < N_ATOMS) ? 16 : 0;
            asm volatile("cp.async.ca.shared.global [%0], [%1], 16, %2;\n"
                         :: "r"(dst), "l"(src), "r"(sz));
        }
        #pragma unroll
        for (int j = 0; j < 2; j++) {
            int f4 = tid + 256 * j;
            int k  = f4 >> 5;
            int nq = (f4 & 31) * 4;
            const float* src = B + (size_t)(kb * BK + k) * HIDDEN + n0 + nq;
            uint32_t dst = sB + (uint32_t)(buf * BK * BSTRIDE + k * BSTRIDE + nq) * 4u;
            asm volatile("cp.async.ca.shared.global [%0], [%1], 16;\n"
                         :: "r"(dst), "l"(src));
        }
        asm volatile("cp.async.commit_group;\n");
    };

    load_tile(0, 0);
    int buf = 0;
    const int KTILES = HIDDEN / BK;

    for (int kb = 0; kb < KTILES; kb++) {
        if (kb + 1 < KTILES) {
            load_tile(kb + 1, buf ^ 1);
            asm volatile("cp.async.wait_group 1;\n");
        } else {
            asm volatile("cp.async.wait_group 0;\n");
        }
        __syncthreads();

        const float* Ab = &As[buf][0];
        const float* Bb = &Bs[buf][0];
        #pragma unroll
        for (int ks = 0; ks < 2; ks++) {
            const int k = ks * 8;
            uint32_t af[2][4];
            uint32_t bf[8][2];
            #pragma unroll
            for (int mt = 0; mt < 2; mt++) {
                int r0 = wm + mt * 16 + grp;
                af[mt][0] = __float_as_uint(Ab[(r0    ) * ASTRIDE + k + tig    ]);
                af[mt][1] = __float_as_uint(Ab[(r0 + 8) * ASTRIDE + k + tig    ]);
                af[mt][2] = __float_as_uint(Ab[(r0    ) * ASTRIDE + k + tig + 4]);
                af[mt][3] = __float_as_uint(Ab[(r0 + 8) * ASTRIDE + k + tig + 4]);
            }
            #pragma unroll
            for (int nt = 0; nt < 8; nt++) {
                int c = wn + nt * 8 + grp;
                bf[nt][0] = __float_as_uint(Bb[(k + tig    ) * BSTRIDE + c]);
                bf[nt][1] = __float_as_uint(Bb[(k + tig + 4) * BSTRIDE + c]);
            }
            #pragma unroll
            for (int mt = 0; mt < 2; mt++)
                #pragma unroll
                for (int nt = 0; nt < 8; nt++)
                    mma_tf32(acc[mt][nt], af[mt], bf[nt]);
        }
        __syncthreads();
        buf ^= 1;
    }

    #pragma unroll
    for (int mt = 0; mt < 2; mt++) {
        int r0 = m0 + wm + mt * 16 + grp;
        int r1 = r0 + 8;
        #pragma unroll
        for (int nt = 0; nt < 8; nt++) {
            int c = n0 + wn + nt * 8 + tig * 2;
            if (r0 < N_ATOMS) {
                C[(size_t)r0 * HIDDEN + c    ] = silu(acc[mt][nt][0]);
                C[(size_t)r0 * HIDDEN + c + 1] = silu(acc[mt][nt][1]);
            }
            if (r1 < N_ATOMS) {
                C[(size_t)r1 * HIDDEN + c    ] = silu(acc[mt][nt][2]);
                C[(size_t)r1 * HIDDEN + c + 1] = silu(acc[mt][nt][3]);
            }
        }
    }
}

// ---------------- final dot + segment sum ----------------
__global__ void zero_out_kernel(float* out) {
    if (threadIdx.x < N_STRUCT) out[threadIdx.x] = 0.0f;
}

__global__ void reduce_kernel(const float* __restrict__ W2,
                              const int* __restrict__ sid,
                              float* __restrict__ out) {
    const int a = blockIdx.x;
    const int t = threadIdx.x;
    float v = 0.0f;
    #pragma unroll
    for (int p = 0; p < NPSEUDO; p++)
        v += g_h2[((size_t)p * N_ATOMS + a) * HIDDEN + t] * W2[p * HIDDEN + t];

    __shared__ float red[8];
    #pragma unroll
    for (int o = 16; o > 0; o >>= 1) v += __shfl_down_sync(0xffffffffu, v, o);
    if ((t & 31) == 0) red[t >> 5] = v;
    __syncthreads();
    if (t < 8) {
        float s = red[t];
        #pragma unroll
        for (int o = 4; o > 0; o >>= 1) s += __shfl_down_sync(0xffu, s, o);
        if (t == 0) atomicAdd(&out[sid[a]], s);
    }
}

// ---------------- launch ----------------
extern "C" void kernel_launch(void* const* d_in, const int* in_sizes, int n_in,
                              void* d_out, int out_size) {
    const float* c0      = (const float*)d_in[0];
    const float* c1      = (const float*)d_in[1];
    const float* c2      = (const float*)d_in[2];
    const float* c3      = (const float*)d_in[3];
    const int*   species = (const int*)d_in[4];
    const int*   sid     = (const int*)d_in[5];
    const float* combW   = (const float*)d_in[6];
    const float* W0      = (const float*)d_in[7];
    const float* W1      = (const float*)d_in[8];
    const float* W2      = (const float*)d_in[9];
    float* out = (float*)d_out;

    static bool attr_set = false;
    if (!attr_set) {
        cudaFuncSetAttribute(gemm0_kernel,
                             cudaFuncAttributeMaxDynamicSharedMemorySize, G0_DSMEM);
        attr_set = true;
    }

    {
        dim3 g(NPACK, NPSEUDO);
        convert_w0_kernel<<<g, 256>>>(W0);
    }
    convert_w1_kernel<<<(NPSEUDO * HIDDEN * HIDDEN + 255) / 256, 256>>>(W1);

    features_kernel<<<N_ATOMS, 256>>>(c0, c1, c2, c3);

    {
        // p fastest: the 4 CTAs sharing an A (features) tile are co-resident in L2
        dim3 g(NPSEUDO, (N_ATOMS + 127) / 128);
        gemm0_kernel<<<g, 256, G0_DSMEM>>>(combW, species);
    }

    {
        dim3 g((N_ATOMS + BM - 1) / BM, HIDDEN / BN, NPSEUDO);
        gemm1_kernel<<<g, 256>>>();
    }

    zero_out_kernel<<<1, 128>>>(out);
    reduce_kernel<<<N_ATOMS, 256>>>(W2, sid, out);
}

// round 4
// speedup vs baseline: 1.6270x; 1.0997x over previous
#include <cuda_runtime.h>
#include <cstdint>
#include <math.h>

#define N_ATOMS  10000
#define N_STRUCT 100
#define NPSEUDO  4
#define NSPECIES 4
#define NFEAT    4096
#define HIDDEN   256
#define NPACK    2112            // 4 * 528 triangular packing
#define KT0      (NPACK / 32)    // 66 k-tiles of 32
#define MBLK     79              // ceil(10000/128) atom blocks
#define APAD     (MBLK * 128)    // 10112

// ---------------- scratch (static device globals; no allocation) ----------------
// fragment-major feature tensor: [b128][kt][b16(8)][ks(4)][lane(32)][slot(4)]
__device__ float g_featP[(size_t)MBLK * KT0 * 4096];                  // 85.4 MB
// fragment-major symmetrized W0: [p][kt][nt(32)][ks(4)][lane(32)][khalf(2)]
__device__ float g_W0sP[(size_t)NPSEUDO * KT0 * 8192];                // 8.7 MB
__device__ float g_h1[(size_t)NPSEUDO * N_ATOMS * HIDDEN];            // 41 MB
__device__ float g_h2[(size_t)NPSEUDO * N_ATOMS * HIDDEN];            // 41 MB
__device__ float g_W1t[(size_t)NPSEUDO * HIDDEN * HIDDEN];            // 1 MB

__device__ __forceinline__ float to_tf32(float x) {
    uint32_t u;
    asm("cvt.rna.tf32.f32 %0, %1;" : "=r"(u) : "f"(x));
    return __uint_as_float(u);
}
__device__ __forceinline__ float silu(float x) { return x / (1.0f + expf(-x)); }

__device__ __forceinline__ uint32_t smem_u32(const void* p) {
    uint32_t a;
    asm("{ .reg .u64 t; cvta.to.shared.u64 t, %1; cvt.u32.u64 %0, t; }" : "=r"(a) : "l"(p));
    return a;
}

// triangular decode: t2 in [0,528) -> (q, r), q<=r<32
__device__ __forceinline__ void tri_decode(int t2, int& q, int& r) {
    q = (int)((65.0f - sqrtf(4225.0f - 8.0f * (float)t2)) * 0.5f);
    if (q < 0) q = 0;
    while (q * (65 - q) / 2 > t2) q--;
    while ((q + 1) * (64 - q) / 2 <= t2) q++;
    r = q + (t2 - q * (65 - q) / 2);
}

// ---------------- symmetrized + fragment-permuted W0 ----------------
__global__ void convert_w0_kernel(const float* __restrict__ W0) {
    const int c   = threadIdx.x;             // hidden col 0..255
    const int k   = blockIdx.x;              // packed k 0..2111
    const int p   = blockIdx.y;
    const int l   = k / 528;
    const int t2  = k - l * 528;
    int q, r;
    tri_decode(t2, q, r);
    const size_t base = (size_t)p * NFEAT * HIDDEN;
    float v = W0[base + (size_t)(l * 1024 + q * 32 + r) * HIDDEN + c];
    if (q != r) v += W0[base + (size_t)(l * 1024 + r * 32 + q) * HIDDEN + c];

    const int kt = k >> 5, ks = (k >> 3) & 3, kin = k & 7;
    const int tig = kin & 3, khalf = kin >> 2;
    const int nt = c >> 3, grp = c & 7, lane = grp * 4 + tig;
    const size_t off = ((((size_t)(p * KT0 + kt) * 32 + nt) * 4 + ks) * 32 + lane) * 2 + khalf;
    g_W0sP[off] = to_tf32(v);
}

__global__ void convert_w1_kernel(const float* __restrict__ W1) {
    size_t i = (size_t)blockIdx.x * 256 + threadIdx.x;
    const size_t n1 = (size_t)NPSEUDO * HIDDEN * HIDDEN;
    if (i < n1) g_W1t[i] = to_tf32(W1[i]);
}

// ---------------- packed power spectrum -> fragment-permuted features ----------------
__global__ void features_kernel(const float* __restrict__ c0,
                                const float* __restrict__ c1,
                                const float* __restrict__ c2,
                                const float* __restrict__ c3) {
    __shared__ float sc[512];
    const int a = blockIdx.x;           // 0..APAD-1 (>=N_ATOMS -> zero pad)
    const int t = threadIdx.x;
    const bool valid = (a < N_ATOMS);
    if (valid) {
        #pragma unroll
        for (int j = 0; j < 2; j++) {
            int idx = t + 256 * j;
            float v;
            if (idx < 32)        v = c0[(size_t)a * 32  + idx];
            else if (idx < 128)  v = c1[(size_t)a * 96  + (idx - 32)];
            else if (idx < 288)  v = c2[(size_t)a * 160 + (idx - 128)];
            else                 v = c3[(size_t)a * 224 + (idx - 288)];
            sc[idx] = v;
        }
        __syncthreads();
    }
    const int   loff[4] = {0, 32, 128, 288};
    const float cg[4]   = {1.0f, 0.57735026919f, 0.44721359550f, 0.37796447301f};

    const int b128 = a >> 7, row = a & 127;
    const int b16 = row >> 4, r16 = row & 15;
    const int grp = r16 & 7, half = r16 >> 3;

    #pragma unroll
    for (int j = 0; j < 9; j++) {
        int k = t + 256 * j;
        if (k < NPACK) {
            float val = 0.0f;
            if (valid) {
                int l  = k / 528;
                int t2 = k - l * 528;
                int q, r;
                tri_decode(t2, q, r);
                const float* cl = sc + loff[l];
                int nm = 2 * l + 1;
                float s = 0.0f;
                for (int m = 0; m < nm; m++) s += cl[m * 32 + q] * cl[m * 32 + r];
                val = to_tf32(cg[l] * s);
            }
            int kt = k >> 5, ks = (k >> 3) & 3, kin = k & 7;
            int tig = kin & 3, khalf = kin >> 2;
            int lane = grp * 4 + tig;
            int slot = half + 2 * khalf;
            size_t off = ((((size_t)(b128 * KT0 + kt) * 8 + b16) * 4 + ks) * 32 + lane) * 4 + slot;
            g_featP[off] = val;
        }
    }
}

// ---------------- tf32 mma helper ----------------
__device__ __forceinline__ void mma_tf32(float c[4], const uint32_t a[4], const uint32_t b[2]) {
    asm volatile(
        "mma.sync.aligned.m16n8k8.row.col.f32.tf32.tf32.f32 "
        "{%0,%1,%2,%3}, {%4,%5,%6,%7}, {%8,%9}, {%0,%1,%2,%3};\n"
        : "+f"(c[0]), "+f"(c[1]), "+f"(c[2]), "+f"(c[3])
        : "r"(a[0]), "r"(a[1]), "r"(a[2]), "r"(a[3]), "r"(b[0]), "r"(b[1]));
}

// ================= GEMM0: h1[p] = silu(pw * feat @ W0s[p]) =================
// BM=128, BN=256, BK=32, fragment-major smem (pure linear copies).
// 8 warps: 4 along M x 2 along N; warp tile 32x128.
#define G0_AFL   4096                       // floats per A k-tile (16KB)
#define G0_BFL   8192                       // floats per B k-tile (32KB)
#define G0_STFL  (G0_AFL + G0_BFL)          // 12288 floats (48KB)
#define G0_STAGES 3
#define G0_DSMEM (G0_STAGES * G0_STFL * 4)  // 144KB

__global__ void __launch_bounds__(256, 1)
gemm0_kernel(const float* __restrict__ combW, const int* __restrict__ species) {
    extern __shared__ float dsm[];

    const int p  = blockIdx.x;
    const int b128 = blockIdx.y;
    const int m0 = b128 * 128;

    const float* Ag = g_featP + (size_t)b128 * KT0 * G0_AFL;
    const float* Bg = g_W0sP  + (size_t)p    * KT0 * G0_BFL;
    float*       C  = g_h1    + (size_t)p * N_ATOMS * HIDDEN;

    const int tid  = threadIdx.x;
    const int warp = tid >> 5;
    const int lane = tid & 31;
    const int grp  = lane >> 2;
    const int tig  = lane & 3;
    const int wmB  = (warp & 3) * 2;     // m16-block base (2 per warp)
    const int wnB  = (warp >> 2) * 16;   // n8-block base (16 per warp)

    float acc[2][16][4];
    #pragma unroll
    for (int mt = 0; mt < 2; mt++)
        #pragma unroll
        for (int nt = 0; nt < 16; nt++)
            #pragma unroll
            for (int i = 0; i < 4; i++) acc[mt][nt][i] = 0.0f;

    const uint32_t sbase = smem_u32(dsm);

    // linear 48KB copy per k-tile: 3072 x 16B, 12 per thread
    auto load_tile = [&](int kt, int b) {
        const float4* srcA = (const float4*)(Ag + (size_t)kt * G0_AFL);
        const float4* srcB = (const float4*)(Bg + (size_t)kt * G0_BFL);
        const uint32_t dst0 = sbase + (uint32_t)b * (G0_STFL * 4);
        #pragma unroll
        for (int j = 0; j < 12; j++) {
            int c = tid + 256 * j;
            const float4* src = (c < 1024) ? (srcA + c) : (srcB + (c - 1024));
            uint32_t dst = dst0 + (uint32_t)c * 16u;
            asm volatile("cp.async.ca.shared.global [%0], [%1], 16;\n"
                         :: "r"(dst), "l"(src));
        }
        asm volatile("cp.async.commit_group;\n");
    };

    load_tile(0, 0);
    load_tile(1, 1);

    for (int kt = 0; kt < KT0; kt++) {
        const int b = kt % G0_STAGES;
        if (kt + 2 < KT0) {
            load_tile(kt + 2, (kt + 2) % G0_STAGES);
            asm volatile("cp.async.wait_group 2;\n");
        } else if (kt + 1 < KT0) {
            asm volatile("cp.async.wait_group 1;\n");
        } else {
            asm volatile("cp.async.wait_group 0;\n");
        }
        __syncthreads();

        const float4* Af = (const float4*)(dsm + (size_t)b * G0_STFL);
        const float2* Bf = (const float2*)(dsm + (size_t)b * G0_STFL + G0_AFL);

        #pragma unroll
        for (int ks = 0; ks < 4; ks++) {
            float4 a0 = Af[((wmB    ) * 4 + ks) * 32 + lane];
            float4 a1 = Af[((wmB + 1) * 4 + ks) * 32 + lane];
            const uint32_t* af0 = (const uint32_t*)&a0;
            const uint32_t* af1 = (const uint32_t*)&a1;
            float2 bv[16];
            #pragma unroll
            for (int nt = 0; nt < 16; nt++)
                bv[nt] = Bf[((wnB + nt) * 4 + ks) * 32 + lane];
            #pragma unroll
            for (int nt = 0; nt < 16; nt++) {
                const uint32_t* bf = (const uint32_t*)&bv[nt];
                mma_tf32(acc[0][nt], af0, bf);
                mma_tf32(acc[1][nt], af1, bf);
            }
        }
        __syncthreads();
    }

    // epilogue: silu(pw * acc); row r0 = m0 + (wmB+mt)*16 + grp (+8)
    #pragma unroll
    for (int mt = 0; mt < 2; mt++) {
        int r0 = m0 + (wmB + mt) * 16 + grp;
        int r1 = r0 + 8;
        float pw0 = 0.0f, pw1 = 0.0f;
        if (r0 < N_ATOMS) pw0 = combW[p * NSPECIES + species[r0]];
        if (r1 < N_ATOMS) pw1 = combW[p * NSPECIES + species[r1]];
        #pragma unroll
        for (int nt = 0; nt < 16; nt++) {
            int c = (wnB + nt) * 8 + tig * 2;
            if (r0 < N_ATOMS) {
                C[(size_t)r0 * HIDDEN + c    ] = silu(acc[mt][nt][0] * pw0);
                C[(size_t)r0 * HIDDEN + c + 1] = silu(acc[mt][nt][1] * pw0);
            }
            if (r1 < N_ATOMS) {
                C[(size_t)r1 * HIDDEN + c    ] = silu(acc[mt][nt][2] * pw1);
                C[(size_t)r1 * HIDDEN + c + 1] = silu(acc[mt][nt][3] * pw1);
            }
        }
    }
}

// ================= GEMM1: h2[p] = silu(h1[p] @ W1t[p]) =================
#define BM 128
#define BN 128
#define BK 16
#define ASTRIDE 20
#define BSTRIDE 136

__global__ void __launch_bounds__(256, 2)
gemm1_kernel() {
    __shared__ float As[2][BM * ASTRIDE];
    __shared__ float Bs[2][BK * BSTRIDE];

    const int p  = blockIdx.z;
    const int m0 = blockIdx.x * BM;
    const int n0 = blockIdx.y * BN;

    const float* A = g_h1  + (size_t)p * N_ATOMS * HIDDEN;
    const float* B = g_W1t + (size_t)p * HIDDEN * HIDDEN;
    float*       C = g_h2  + (size_t)p * N_ATOMS * HIDDEN;

    const int tid  = threadIdx.x;
    const int warp = tid >> 5;
    const int lane = tid & 31;
    const int grp  = lane >> 2;
    const int tig  = lane & 3;
    const int wm   = (warp & 3) * 32;
    const int wn   = (warp >> 2) * 64;

    float acc[2][8][4];
    #pragma unroll
    for (int mt = 0; mt < 2; mt++)
        #pragma unroll
        for (int nt = 0; nt < 8; nt++)
            #pragma unroll
            for (int i = 0; i < 4; i++) acc[mt][nt][i] = 0.0f;

    const uint32_t sA = smem_u32(&As[0][0]);
    const uint32_t sB = smem_u32(&Bs[0][0]);

    auto load_tile = [&](int kb, int buf) {
        #pragma unroll
        for (int j = 0; j < 2; j++) {
            int f4 = tid + 256 * j;
            int m  = f4 >> 2;
            int kq = (f4 & 3) * 4;
            int row = m0 + m;
            const float* src = A + (size_t)row * HIDDEN + kb * BK + kq;
            uint32_t dst = sA + (uint32_t)(buf * BM * ASTRIDE + m * ASTRIDE + kq) * 4u;
            int sz = (row < N_ATOMS) ? 16 : 0;
            asm volatile("cp.async.ca.shared.global [%0], [%1], 16, %2;\n"
                         :: "r"(dst), "l"(src), "r"(sz));
        }
        #pragma unroll
        for (int j = 0; j < 2; j++) {
            int f4 = tid + 256 * j;
            int k  = f4 >> 5;
            int nq = (f4 & 31) * 4;
            const float* src = B + (size_t)(kb * BK + k) * HIDDEN + n0 + nq;
            uint32_t dst = sB + (uint32_t)(buf * BK * BSTRIDE + k * BSTRIDE + nq) * 4u;
            asm volatile("cp.async.ca.shared.global [%0], [%1], 16;\n"
                         :: "r"(dst), "l"(src));
        }
        asm volatile("cp.async.commit_group;\n");
    };

    load_tile(0, 0);
    int buf = 0;
    const int KTILES = HIDDEN / BK;

    for (int kb = 0; kb < KTILES; kb++) {
        if (kb + 1 < KTILES) {
            load_tile(kb + 1, buf ^ 1);
            asm volatile("cp.async.wait_group 1;\n");
        } else {
            asm volatile("cp.async.wait_group 0;\n");
        }
        __syncthreads();

        const float* Ab = &As[buf][0];
        const float* Bb = &Bs[buf][0];
        #pragma unroll
        for (int ks = 0; ks < 2; ks++) {
            const int k = ks * 8;
            uint32_t af[2][4];
            uint32_t bf[8][2];
            #pragma unroll
            for (int mt = 0; mt < 2; mt++) {
                int r0 = wm + mt * 16 + grp;
                af[mt][0] = __float_as_uint(Ab[(r0    ) * ASTRIDE + k + tig    ]);
                af[mt][1] = __float_as_uint(Ab[(r0 + 8) * ASTRIDE + k + tig    ]);
                af[mt][2] = __float_as_uint(Ab[(r0    ) * ASTRIDE + k + tig + 4]);
                af[mt][3] = __float_as_uint(Ab[(r0 + 8) * ASTRIDE + k + tig + 4]);
            }
            #pragma unroll
            for (int nt = 0; nt < 8; nt++) {
                int c = wn + nt * 8 + grp;
                bf[nt][0] = __float_as_uint(Bb[(k + tig    ) * BSTRIDE + c]);
                bf[nt][1] = __float_as_uint(Bb[(k + tig + 4) * BSTRIDE + c]);
            }
            #pragma unroll
            for (int mt = 0; mt < 2; mt++)
                #pragma unroll
                for (int nt = 0; nt < 8; nt++)
                    mma_tf32(acc[mt][nt], af[mt], bf[nt]);
        }
        __syncthreads();
        buf ^= 1;
    }

    #pragma unroll
    for (int mt = 0; mt < 2; mt++) {
        int r0 = m0 + wm + mt * 16 + grp;
        int r1 = r0 + 8;
        #pragma unroll
        for (int nt = 0; nt < 8; nt++) {
            int c = n0 + wn + nt * 8 + tig * 2;
            if (r0 < N_ATOMS) {
                C[(size_t)r0 * HIDDEN + c    ] = silu(acc[mt][nt][0]);
                C[(size_t)r0 * HIDDEN + c + 1] = silu(acc[mt][nt][1]);
            }
            if (r1 < N_ATOMS) {
                C[(size_t)r1 * HIDDEN + c    ] = silu(acc[mt][nt][2]);
                C[(size_t)r1 * HIDDEN + c + 1] = silu(acc[mt][nt][3]);
            }
        }
    }
}

// ---------------- final dot + segment sum ----------------
__global__ void zero_out_kernel(float* out) {
    if (threadIdx.x < N_STRUCT) out[threadIdx.x] = 0.0f;
}

__global__ void reduce_kernel(const float* __restrict__ W2,
                              const int* __restrict__ sid,
                              float* __restrict__ out) {
    const int a = blockIdx.x;
    const int t = threadIdx.x;
    float v = 0.0f;
    #pragma unroll
    for (int p = 0; p < NPSEUDO; p++)
        v += g_h2[((size_t)p * N_ATOMS + a) * HIDDEN + t] * W2[p * HIDDEN + t];

    __shared__ float red[8];
    #pragma unroll
    for (int o = 16; o > 0; o >>= 1) v += __shfl_down_sync(0xffffffffu, v, o);
    if ((t & 31) == 0) red[t >> 5] = v;
    __syncthreads();
    if (t < 8) {
        float s = red[t];
        #pragma unroll
        for (int o = 4; o > 0; o >>= 1) s += __shfl_down_sync(0xffu, s, o);
        if (t == 0) atomicAdd(&out[sid[a]], s);
    }
}

// ---------------- launch ----------------
extern "C" void kernel_launch(void* const* d_in, const int* in_sizes, int n_in,
                              void* d_out, int out_size) {
    const float* c0      = (const float*)d_in[0];
    const float* c1      = (const float*)d_in[1];
    const float* c2      = (const float*)d_in[2];
    const float* c3      = (const float*)d_in[3];
    const int*   species = (const int*)d_in[4];
    const int*   sid     = (const int*)d_in[5];
    const float* combW   = (const float*)d_in[6];
    const float* W0      = (const float*)d_in[7];
    const float* W1      = (const float*)d_in[8];
    const float* W2      = (const float*)d_in[9];
    float* out = (float*)d_out;

    static bool attr_set = false;
    if (!attr_set) {
        cudaFuncSetAttribute(gemm0_kernel,
                             cudaFuncAttributeMaxDynamicSharedMemorySize, G0_DSMEM);
        attr_set = true;
    }

    {
        dim3 g(NPACK, NPSEUDO);
        convert_w0_kernel<<<g, 256>>>(W0);
    }
    convert_w1_kernel<<<(NPSEUDO * HIDDEN * HIDDEN + 255) / 256, 256>>>(W1);

    features_kernel<<<APAD, 256>>>(c0, c1, c2, c3);

    {
        dim3 g(NPSEUDO, MBLK);   // p fastest: 4 sharers of each A tile co-resident
        gemm0_kernel<<<g, 256, G0_DSMEM>>>(combW, species);
    }

    {
        dim3 g((N_ATOMS + BM - 1) / BM, HIDDEN / BN, NPSEUDO);
        gemm1_kernel<<<g, 256>>>();
    }

    zero_out_kernel<<<1, 128>>>(out);
    reduce_kernel<<<N_ATOMS, 256>>>(W2, sid, out);
}

// round 5
// speedup vs baseline: 1.6848x; 1.0355x over previous
#include <cuda_runtime.h>
#include <cstdint>
#include <math.h>

#define N_ATOMS  10000
#define N_STRUCT 100
#define NPSEUDO  4
#define NSPECIES 4
#define NFEAT    4096
#define HIDDEN   256
#define NPACK    2112            // 4 * 528 triangular packing
#define KT0      (NPACK / 32)    // 66 k-tiles of 32
#define MBLK64   157             // ceil(10000/64)
#define APAD     (MBLK64 * 64)   // 10048

// ---------------- scratch (static device globals; no allocation) ----------------
// fragment-major features: [b64][kt][b16(4)][ks(4)][lane(32)][slot(4)]
__device__ float g_featP[(size_t)MBLK64 * KT0 * 2048];                // 84.9 MB
// fragment-major symmetrized W0: [p][kt][nt(32)][ks(4)][lane(32)][khalf(2)]
__device__ float g_W0sP[(size_t)NPSEUDO * KT0 * 8192];                // 8.7 MB
__device__ float g_h1[(size_t)NPSEUDO * N_ATOMS * HIDDEN];            // 41 MB
__device__ float g_h2[(size_t)NPSEUDO * N_ATOMS * HIDDEN];            // 41 MB
__device__ float g_W1t[(size_t)NPSEUDO * HIDDEN * HIDDEN];            // 1 MB

__device__ __forceinline__ float to_tf32(float x) {
    uint32_t u;
    asm("cvt.rna.tf32.f32 %0, %1;" : "=r"(u) : "f"(x));
    return __uint_as_float(u);
}
__device__ __forceinline__ float silu(float x) { return x / (1.0f + expf(-x)); }

__device__ __forceinline__ uint32_t smem_u32(const void* p) {
    uint32_t a;
    asm("{ .reg .u64 t; cvta.to.shared.u64 t, %1; cvt.u32.u64 %0, t; }" : "=r"(a) : "l"(p));
    return a;
}

// triangular decode: t2 in [0,528) -> (q, r), q<=r<32
__device__ __forceinline__ void tri_decode(int t2, int& q, int& r) {
    q = (int)((65.0f - sqrtf(4225.0f - 8.0f * (float)t2)) * 0.5f);
    if (q < 0) q = 0;
    while (q * (65 - q) / 2 > t2) q--;
    while ((q + 1) * (64 - q) / 2 <= t2) q++;
    r = q + (t2 - q * (65 - q) / 2);
}

// ---------------- symmetrized + fragment-permuted W0 ----------------
__global__ void convert_w0_kernel(const float* __restrict__ W0) {
    const int c   = threadIdx.x;             // hidden col 0..255
    const int k   = blockIdx.x;              // packed k 0..2111
    const int p   = blockIdx.y;
    const int l   = k / 528;
    const int t2  = k - l * 528;
    int q, r;
    tri_decode(t2, q, r);
    const size_t base = (size_t)p * NFEAT * HIDDEN;
    float v = W0[base + (size_t)(l * 1024 + q * 32 + r) * HIDDEN + c];
    if (q != r) v += W0[base + (size_t)(l * 1024 + r * 32 + q) * HIDDEN + c];

    const int kt = k >> 5, ks = (k >> 3) & 3, kin = k & 7;
    const int tig = kin & 3, khalf = kin >> 2;
    const int nt = c >> 3, grp = c & 7, lane = grp * 4 + tig;
    const size_t off = ((((size_t)(p * KT0 + kt) * 32 + nt) * 4 + ks) * 32 + lane) * 2 + khalf;
    g_W0sP[off] = to_tf32(v);
}

__global__ void convert_w1_kernel(const float* __restrict__ W1) {
    size_t i = (size_t)blockIdx.x * 256 + threadIdx.x;
    const size_t n1 = (size_t)NPSEUDO * HIDDEN * HIDDEN;
    if (i < n1) g_W1t[i] = to_tf32(W1[i]);
}

// ---------------- packed power spectrum -> fragment-permuted features ----------------
__global__ void features_kernel(const float* __restrict__ c0,
                                const float* __restrict__ c1,
                                const float* __restrict__ c2,
                                const float* __restrict__ c3) {
    __shared__ float sc[512];
    const int a = blockIdx.x;           // 0..APAD-1 (>=N_ATOMS -> zero pad)
    const int t = threadIdx.x;
    const bool valid = (a < N_ATOMS);
    if (valid) {
        #pragma unroll
        for (int j = 0; j < 2; j++) {
            int idx = t + 256 * j;
            float v;
            if (idx < 32)        v = c0[(size_t)a * 32  + idx];
            else if (idx < 128)  v = c1[(size_t)a * 96  + (idx - 32)];
            else if (idx < 288)  v = c2[(size_t)a * 160 + (idx - 128)];
            else                 v = c3[(size_t)a * 224 + (idx - 288)];
            sc[idx] = v;
        }
        __syncthreads();
    }
    const int   loff[4] = {0, 32, 128, 288};
    const float cg[4]   = {1.0f, 0.57735026919f, 0.44721359550f, 0.37796447301f};

    const int b64 = a >> 6, row = a & 63;
    const int b16 = row >> 4, r16 = row & 15;
    const int grp = r16 & 7, half = r16 >> 3;

    #pragma unroll
    for (int j = 0; j < 9; j++) {
        int k = t + 256 * j;
        if (k < NPACK) {
            float val = 0.0f;
            if (valid) {
                int l  = k / 528;
                int t2 = k - l * 528;
                int q, r;
                tri_decode(t2, q, r);
                const float* cl = sc + loff[l];
                int nm = 2 * l + 1;
                float s = 0.0f;
                for (int m = 0; m < nm; m++) s += cl[m * 32 + q] * cl[m * 32 + r];
                val = to_tf32(cg[l] * s);
            }
            int kt = k >> 5, ks = (k >> 3) & 3, kin = k & 7;
            int tig = kin & 3, khalf = kin >> 2;
            int lane = grp * 4 + tig;
            int slot = half + 2 * khalf;
            size_t off = ((((size_t)(b64 * KT0 + kt) * 4 + b16) * 4 + ks) * 32 + lane) * 4 + slot;
            g_featP[off] = val;
        }
    }
}

// ---------------- tf32 mma helper ----------------
__device__ __forceinline__ void mma_tf32(float c[4], const uint32_t a[4], const uint32_t b[2]) {
    asm volatile(
        "mma.sync.aligned.m16n8k8.row.col.f32.tf32.tf32.f32 "
        "{%0,%1,%2,%3}, {%4,%5,%6,%7}, {%8,%9}, {%0,%1,%2,%3};\n"
        : "+f"(c[0]), "+f"(c[1]), "+f"(c[2]), "+f"(c[3])
        : "r"(a[0]), "r"(a[1]), "r"(a[2]), "r"(a[3]), "r"(b[0]), "r"(b[1]));
}

// ================= GEMM0: h1[p] = silu(pw * feat @ W0s[p]) =================
// Tile 64x128, CTA=128 threads (4 warps: 2M x 2N, warp tile 32x64), BK=32.
// 3 CTAs/SM target -> 12 warps/SM. Fragment-major smem, ks-prefetched frags.
#define G0_AFL   2048                       // floats per A k-tile (8KB)
#define G0_BFL   4096                       // floats per B k-tile (16KB)
#define G0_STFL  (G0_AFL + G0_BFL)          // 6144 floats (24KB)
#define G0_STAGES 3
#define G0_DSMEM (G0_STAGES * G0_STFL * 4)  // 72KB

__global__ void __launch_bounds__(128, 3)
gemm0_kernel(const float* __restrict__ combW, const int* __restrict__ species) {
    extern __shared__ float dsm[];

    const int p   = blockIdx.x >> 1;         // pseudo species
    const int nh  = blockIdx.x & 1;          // hidden half (128 cols)
    const int b64 = blockIdx.y;
    const int m0  = b64 * 64;

    const float* Ag = g_featP + (size_t)b64 * KT0 * G0_AFL;
    const float* Bg = g_W0sP  + (size_t)p * KT0 * 8192 + (size_t)nh * G0_BFL;
    float*       C  = g_h1    + (size_t)p * N_ATOMS * HIDDEN + nh * 128;

    const int tid  = threadIdx.x;
    const int warp = tid >> 5;
    const int lane = tid & 31;
    const int grp  = lane >> 2;
    const int tig  = lane & 3;
    const int wmB  = (warp & 1) * 2;     // m16-block base (2 per warp)
    const int wnB  = (warp >> 1) * 8;    // n8-block base (8 per warp)

    float acc[2][8][4];
    #pragma unroll
    for (int mt = 0; mt < 2; mt++)
        #pragma unroll
        for (int nt = 0; nt < 8; nt++)
            #pragma unroll
            for (int i = 0; i < 4; i++) acc[mt][nt][i] = 0.0f;

    const uint32_t sbase = smem_u32(dsm);

    // linear 24KB copy per k-tile: 1536 x 16B, 12 per thread
    auto load_tile = [&](int kt, int b) {
        const float4* srcA = (const float4*)(Ag + (size_t)kt * G0_AFL);
        const float4* srcB = (const float4*)(Bg + (size_t)kt * 8192);
        const uint32_t dst0 = sbase + (uint32_t)b * (G0_STFL * 4);
        #pragma unroll
        for (int j = 0; j < 12; j++) {
            int c = tid + 128 * j;
            const float4* src = (c < 512) ? (srcA + c) : (srcB + (c - 512));
            uint32_t dst = dst0 + (uint32_t)c * 16u;
            asm volatile("cp.async.ca.shared.global [%0], [%1], 16;\n"
                         :: "r"(dst), "l"(src));
        }
        asm volatile("cp.async.commit_group;\n");
    };

    load_tile(0, 0);
    load_tile(1, 1);

    for (int kt = 0; kt < KT0; kt++) {
        const int b = kt % G0_STAGES;
        if (kt + 2 < KT0) {
            load_tile(kt + 2, (kt + 2) % G0_STAGES);
            asm volatile("cp.async.wait_group 2;\n");
        } else if (kt + 1 < KT0) {
            asm volatile("cp.async.wait_group 1;\n");
        } else {
            asm volatile("cp.async.wait_group 0;\n");
        }
        __syncthreads();

        const float4* Af = (const float4*)(dsm + (size_t)b * G0_STFL);
        const float2* Bf = (const float2*)(dsm + (size_t)b * G0_STFL + G0_AFL);

        // ks-level fragment double buffering
        float4 a0[2], a1[2];
        float2 bv[2][8];
        a0[0] = Af[((wmB    ) * 4 + 0) * 32 + lane];
        a1[0] = Af[((wmB + 1) * 4 + 0) * 32 + lane];
        #pragma unroll
        for (int nt = 0; nt < 8; nt++)
            bv[0][nt] = Bf[((wnB + nt) * 4 + 0) * 32 + lane];

        #pragma unroll
        for (int ks = 0; ks < 4; ks++) {
            const int cur = ks & 1, nxt = cur ^ 1;
            if (ks < 3) {
                a0[nxt] = Af[((wmB    ) * 4 + ks + 1) * 32 + lane];
                a1[nxt] = Af[((wmB + 1) * 4 + ks + 1) * 32 + lane];
                #pragma unroll
                for (int nt = 0; nt < 8; nt++)
                    bv[nxt][nt] = Bf[((wnB + nt) * 4 + ks + 1) * 32 + lane];
            }
            const uint32_t* af0 = (const uint32_t*)&a0[cur];
            const uint32_t* af1 = (const uint32_t*)&a1[cur];
            #pragma unroll
            for (int nt = 0; nt < 8; nt++) {
                const uint32_t* bf = (const uint32_t*)&bv[cur][nt];
                mma_tf32(acc[0][nt], af0, bf);
                mma_tf32(acc[1][nt], af1, bf);
            }
        }
        __syncthreads();
    }

    // epilogue: silu(pw * acc)
    #pragma unroll
    for (int mt = 0; mt < 2; mt++) {
        int r0 = m0 + (wmB + mt) * 16 + grp;
        int r1 = r0 + 8;
        float pw0 = 0.0f, pw1 = 0.0f;
        if (r0 < N_ATOMS) pw0 = combW[p * NSPECIES + species[r0]];
        if (r1 < N_ATOMS) pw1 = combW[p * NSPECIES + species[r1]];
        #pragma unroll
        for (int nt = 0; nt < 8; nt++) {
            int c = (wnB + nt) * 8 + tig * 2;
            if (r0 < N_ATOMS) {
                C[(size_t)r0 * HIDDEN + c    ] = silu(acc[mt][nt][0] * pw0);
                C[(size_t)r0 * HIDDEN + c + 1] = silu(acc[mt][nt][1] * pw0);
            }
            if (r1 < N_ATOMS) {
                C[(size_t)r1 * HIDDEN + c    ] = silu(acc[mt][nt][2] * pw1);
                C[(size_t)r1 * HIDDEN + c + 1] = silu(acc[mt][nt][3] * pw1);
            }
        }
    }
}

// ================= GEMM1: h2[p] = silu(h1[p] @ W1t[p]) =================
#define BM 128
#define BN 128
#define BK 16
#define ASTRIDE 20
#define BSTRIDE 136

__global__ void __launch_bounds__(256, 2)
gemm1_kernel() {
    __shared__ float As[2][BM * ASTRIDE];
    __shared__ float Bs[2][BK * BSTRIDE];

    const int p  = blockIdx.z;
    const int m0 = blockIdx.x * BM;
    const int n0 = blockIdx.y * BN;

    const float* A = g_h1  + (size_t)p * N_ATOMS * HIDDEN;
    const float* B = g_W1t + (size_t)p * HIDDEN * HIDDEN;
    float*       C = g_h2  + (size_t)p * N_ATOMS * HIDDEN;

    const int tid  = threadIdx.x;
    const int warp = tid >> 5;
    const int lane = tid & 31;
    const int grp  = lane >> 2;
    const int tig  = lane & 3;
    const int wm   = (warp & 3) * 32;
    const int wn   = (warp >> 2) * 64;

    float acc[2][8][4];
    #pragma unroll
    for (int mt = 0; mt < 2; mt++)
        #pragma unroll
        for (int nt = 0; nt < 8; nt++)
            #pragma unroll
            for (int i = 0; i < 4; i++) acc[mt][nt][i] = 0.0f;

    const uint32_t sA = smem_u32(&As[0][0]);
    const uint32_t sB = smem_u32(&Bs[0][0]);

    auto load_tile = [&](int kb, int buf) {
        #pragma unroll
        for (int j = 0; j < 2; j++) {
            int f4 = tid + 256 * j;
            int m  = f4 >> 2;
            int kq = (f4 & 3) * 4;
            int row = m0 + m;
            const float* src = A + (size_t)row * HIDDEN + kb * BK + kq;
            uint32_t dst = sA + (uint32_t)(buf * BM * ASTRIDE + m * ASTRIDE + kq) * 4u;
            int sz = (row < N_ATOMS) ? 16 : 0;
            asm volatile("cp.async.ca.shared.global [%0], [%1], 16, %2;\n"
                         :: "r"(dst), "l"(src), "r"(sz));
        }
        #pragma unroll
        for (int j = 0; j < 2; j++) {
            int f4 = tid + 256 * j;
            int k  = f4 >> 5;
            int nq = (f4 & 31) * 4;
            const float* src = B + (size_t)(kb * BK + k) * HIDDEN + n0 + nq;
            uint32_t dst = sB + (uint32_t)(buf * BK * BSTRIDE + k * BSTRIDE + nq) * 4u;
            asm volatile("cp.async.ca.shared.global [%0], [%1], 16;\n"
                         :: "r"(dst), "l"(src));
        }
        asm volatile("cp.async.commit_group;\n");
    };

    load_tile(0, 0);
    int buf = 0;
    const int KTILES = HIDDEN / BK;

    for (int kb = 0; kb < KTILES; kb++) {
        if (kb + 1 < KTILES) {
            load_tile(kb + 1, buf ^ 1);
            asm volatile("cp.async.wait_group 1;\n");
        } else {
            asm volatile("cp.async.wait_group 0;\n");
        }
        __syncthreads();

        const float* Ab = &As[buf][0];
        const float* Bb = &Bs[buf][0];
        #pragma unroll
        for (int ks = 0; ks < 2; ks++) {
            const int k = ks * 8;
            uint32_t af[2][4];
            uint32_t bf[8][2];
            #pragma unroll
            for (int mt = 0; mt < 2; mt++) {
                int r0 = wm + mt * 16 + grp;
                af[mt][0] = __float_as_uint(Ab[(r0    ) * ASTRIDE + k + tig    ]);
                af[mt][1] = __float_as_uint(Ab[(r0 + 8) * ASTRIDE + k + tig    ]);
                af[mt][2] = __float_as_uint(Ab[(r0    ) * ASTRIDE + k + tig + 4]);
                af[mt][3] = __float_as_uint(Ab[(r0 + 8) * ASTRIDE + k + tig + 4]);
            }
            #pragma unroll
            for (int nt = 0; nt < 8; nt++) {
                int c = wn + nt * 8 + grp;
                bf[nt][0] = __float_as_uint(Bb[(k + tig    ) * BSTRIDE + c]);
                bf[nt][1] = __float_as_uint(Bb[(k + tig + 4) * BSTRIDE + c]);
            }
            #pragma unroll
            for (int mt = 0; mt < 2; mt++)
                #pragma unroll
                for (int nt = 0; nt < 8; nt++)
                    mma_tf32(acc[mt][nt], af[mt], bf[nt]);
        }
        __syncthreads();
        buf ^= 1;
    }

    #pragma unroll
    for (int mt = 0; mt < 2; mt++) {
        int r0 = m0 + wm + mt * 16 + grp;
        int r1 = r0 + 8;
        #pragma unroll
        for (int nt = 0; nt < 8; nt++) {
            int c = n0 + wn + nt * 8 + tig * 2;
            if (r0 < N_ATOMS) {
                C[(size_t)r0 * HIDDEN + c    ] = silu(acc[mt][nt][0]);
                C[(size_t)r0 * HIDDEN + c + 1] = silu(acc[mt][nt][1]);
            }
            if (r1 < N_ATOMS) {
                C[(size_t)r1 * HIDDEN + c    ] = silu(acc[mt][nt][2]);
                C[(size_t)r1 * HIDDEN + c + 1] = silu(acc[mt][nt][3]);
            }
        }
    }
}

// ---------------- final dot + segment sum ----------------
__global__ void zero_out_kernel(float* out) {
    if (threadIdx.x < N_STRUCT) out[threadIdx.x] = 0.0f;
}

__global__ void reduce_kernel(const float* __restrict__ W2,
                              const int* __restrict__ sid,
                              float* __restrict__ out) {
    const int a = blockIdx.x;
    const int t = threadIdx.x;
    float v = 0.0f;
    #pragma unroll
    for (int p = 0; p < NPSEUDO; p++)
        v += g_h2[((size_t)p * N_ATOMS + a) * HIDDEN + t] * W2[p * HIDDEN + t];

    __shared__ float red[8];
    #pragma unroll
    for (int o = 16; o > 0; o >>= 1) v += __shfl_down_sync(0xffffffffu, v, o);
    if ((t & 31) == 0) red[t >> 5] = v;
    __syncthreads();
    if (t < 8) {
        float s = red[t];
        #pragma unroll
        for (int o = 4; o > 0; o >>= 1) s += __shfl_down_sync(0xffu, s, o);
        if (t == 0) atomicAdd(&out[sid[a]], s);
    }
}

// ---------------- launch ----------------
extern "C" void kernel_launch(void* const* d_in, const int* in_sizes, int n_in,
                              void* d_out, int out_size) {
    const float* c0      = (const float*)d_in[0];
    const float* c1      = (const float*)d_in[1];
    const float* c2      = (const float*)d_in[2];
    const float* c3      = (const float*)d_in[3];
    const int*   species = (const int*)d_in[4];
    const int*   sid     = (const int*)d_in[5];
    const float* combW   = (const float*)d_in[6];
    const float* W0      = (const float*)d_in[7];
    const float* W1      = (const float*)d_in[8];
    const float* W2      = (const float*)d_in[9];
    float* out = (float*)d_out;

    static bool attr_set = false;
    if (!attr_set) {
        cudaFuncSetAttribute(gemm0_kernel,
                             cudaFuncAttributeMaxDynamicSharedMemorySize, G0_DSMEM);
        attr_set = true;
    }

    {
        dim3 g(NPACK, NPSEUDO);
        convert_w0_kernel<<<g, 256>>>(W0);
    }
    convert_w1_kernel<<<(NPSEUDO * HIDDEN * HIDDEN + 255) / 256, 256>>>(W1);

    features_kernel<<<APAD, 256>>>(c0, c1, c2, c3);

    {
        // x = p*2 + n-half (8 sharers of each A tile co-resident), y = atom block
        dim3 g(NPSEUDO * 2, MBLK64);
        gemm0_kernel<<<g, 128, G0_DSMEM>>>(combW, species);
    }

    {
        dim3 g((N_ATOMS + BM - 1) / BM, HIDDEN / BN, NPSEUDO);
        gemm1_kernel<<<g, 256>>>();
    }

    zero_out_kernel<<<1, 128>>>(out);
    reduce_kernel<<<N_ATOMS, 256>>>(W2, sid, out);
}

// round 7
// speedup vs baseline: 2.8840x; 1.7118x over previous
#include <cuda_runtime.h>
#include <cuda_fp16.h>
#include <cstdint>
#include <math.h>

#define N_ATOMS  10000
#define N_STRUCT 100
#define NPSEUDO  4
#define NSPECIES 4
#define NFEAT    4096
#define HIDDEN   256
#define NPACK    2112            // 4 * 528 triangular packing
#define KT0      (NPACK / 32)    // 66 k-tiles of 32
#define KT1      (HIDDEN / 32)   // 8
#define MBLK64   157             // ceil(10000/64)
#define APAD     (MBLK64 * 64)   // 10048

// ---------------- scratch (static device globals; no allocation) ----------------
// fp16 fragment-major A (features): [b64][kt][b16(4)][kmma(2)][lane(32)][reg(4)] u32
__device__ uint32_t g_featP[(size_t)MBLK64 * KT0 * 1024];             // 42.4 MB
// fp16 fragment-major B (W0 symmetrized): [p][kt][nt(32)][kmma(2)][lane(32)][khalf(2)] u32
__device__ uint32_t g_W0f[(size_t)NPSEUDO * KT0 * 4096];              // 4.3 MB
__device__ uint32_t g_W1f[(size_t)NPSEUDO * KT1 * 4096];              // 0.5 MB
// fp16 fragment-major h1 (A of GEMM1): [p][b64][kt(8)][b16(4)][kmma(2)][lane(32)][reg(4)]
__device__ uint32_t g_h1f[(size_t)NPSEUDO * MBLK64 * KT1 * 1024];     // 20.6 MB
__device__ __half   g_h2h[(size_t)NPSEUDO * N_ATOMS * HIDDEN];        // 20.5 MB

__device__ __forceinline__ float silu(float x) { return x / (1.0f + expf(-x)); }

__device__ __forceinline__ uint32_t smem_u32(const void* p) {
    uint32_t a;
    asm("{ .reg .u64 t; cvta.to.shared.u64 t, %1; cvt.u32.u64 %0, t; }" : "=r"(a) : "l"(p));
    return a;
}

// triangular decode: t2 in [0,528) -> (q, r), q<=r<32
__device__ __forceinline__ void tri_decode(int t2, int& q, int& r) {
    q = (int)((65.0f - sqrtf(4225.0f - 8.0f * (float)t2)) * 0.5f);
    if (q < 0) q = 0;
    while (q * (65 - q) / 2 > t2) q--;
    while ((q + 1) * (64 - q) / 2 <= t2) q++;
    r = q + (t2 - q * (65 - q) / 2);
}

// B-fragment halfword offset for element (k within 32-tile, col c within 256)
__device__ __forceinline__ size_t b_frag_off(int kt, int kin, int c, int ktiles, int p) {
    int kmma = kin >> 4, k16 = kin & 15;
    int khalf = k16 >> 3, kpos = k16 & 7;
    int tig = kpos >> 1, hw = kpos & 1;
    int nt = c >> 3, grp = c & 7, lane = grp * 4 + tig;
    size_t u32off = ((((size_t)(p * ktiles + kt) * 32 + nt) * 2 + kmma) * 32 + lane) * 2 + khalf;
    return u32off * 2 + hw;
}

// ---------------- W0: symmetrize + fp16 fragment-permute ----------------
__global__ void convert_w0_kernel(const float* __restrict__ W0) {
    const int c = threadIdx.x;               // hidden col
    const int k = blockIdx.x;                // packed k 0..2111
    const int p = blockIdx.y;
    const int l = k / 528;
    const int t2 = k - l * 528;
    int q, r;
    tri_decode(t2, q, r);
    const size_t base = (size_t)p * NFEAT * HIDDEN;
    float v = W0[base + (size_t)(l * 1024 + q * 32 + r) * HIDDEN + c];
    if (q != r) v += W0[base + (size_t)(l * 1024 + r * 32 + q) * HIDDEN + c];
    ((__half*)g_W0f)[b_frag_off(k >> 5, k & 31, c, KT0, p)] = __float2half_rn(v);
}

// ---------------- W1: fp16 fragment-permute ----------------
__global__ void convert_w1_kernel(const float* __restrict__ W1) {
    const int c = threadIdx.x;
    const int k = blockIdx.x;                // 0..255
    const int p = blockIdx.y;
    float v = W1[((size_t)p * HIDDEN + k) * HIDDEN + c];
    ((__half*)g_W1f)[b_frag_off(k >> 5, k & 31, c, KT1, p)] = __float2half_rn(v);
}

// ---------------- packed power spectrum -> fp16 fragment-major features ----------------
__global__ void features_kernel(const float* __restrict__ c0,
                                const float* __restrict__ c1,
                                const float* __restrict__ c2,
                                const float* __restrict__ c3) {
    __shared__ float sc[512];
    const int a = blockIdx.x;
    const int t = threadIdx.x;
    const bool valid = (a < N_ATOMS);
    if (valid) {
        #pragma unroll
        for (int j = 0; j < 2; j++) {
            int idx = t + 256 * j;
            float v;
            if (idx < 32)        v = c0[(size_t)a * 32  + idx];
            else if (idx < 128)  v = c1[(size_t)a * 96  + (idx - 32)];
            else if (idx < 288)  v = c2[(size_t)a * 160 + (idx - 128)];
            else                 v = c3[(size_t)a * 224 + (idx - 288)];
            sc[idx] = v;
        }
        __syncthreads();
    }
    const int   loff[4] = {0, 32, 128, 288};
    const float cg[4]   = {1.0f, 0.57735026919f, 0.44721359550f, 0.37796447301f};

    const int b64 = a >> 6, row = a & 63;
    const int b16 = row >> 4, r16 = row & 15;
    const int grp = r16 & 7, rhalf = r16 >> 3;

    #pragma unroll
    for (int j = 0; j < 9; j++) {
        int k = t + 256 * j;
        if (k < NPACK) {
            float val = 0.0f;
            if (valid) {
                int l  = k / 528;
                int t2 = k - l * 528;
                int q, r;
                tri_decode(t2, q, r);
                const float* cl = sc + loff[l];
                int nm = 2 * l + 1;
                float s = 0.0f;
                for (int m = 0; m < nm; m++) s += cl[m * 32 + q] * cl[m * 32 + r];
                val = cg[l] * s;
            }
            int kt = k >> 5, kin = k & 31;
            int kmma = kin >> 4, k16 = kin & 15;
            int khalf = k16 >> 3, kpos = k16 & 7;
            int tig = kpos >> 1, hw = kpos & 1;
            int lane = grp * 4 + tig;
            int areg = rhalf + 2 * khalf;
            size_t off = (((((size_t)(b64 * KT0 + kt) * 4 + b16) * 2 + kmma) * 32 + lane) * 4 + areg) * 2 + hw;
            ((__half*)g_featP)[off] = __float2half_rn(val);
        }
    }
}

// ---------------- fp16 mma (fp32 accumulate) ----------------
__device__ __forceinline__ void mma_f16(float c[4], const uint32_t a[4], const uint32_t b[2]) {
    asm volatile(
        "mma.sync.aligned.m16n8k16.row.col.f32.f16.f16.f32 "
        "{%0,%1,%2,%3}, {%4,%5,%6,%7}, {%8,%9}, {%0,%1,%2,%3};\n"
        : "+f"(c[0]), "+f"(c[1]), "+f"(c[2]), "+f"(c[3])
        : "r"(a[0]), "r"(a[1]), "r"(a[2]), "r"(a[3]), "r"(b[0]), "r"(b[1]));
}

// ================= unified fp16 GEMM: 64x128 tile, CTA=128 threads =================
// MODE 0: A=featP, B=W0f, C=g_h1f (fragment-major fp16), epi silu(pw*x). KT=66.
// MODE 1: A=g_h1f, B=W1f, C=g_h2h (plain fp16),          epi silu(x).    KT=8.
#define G_STFL   3072                        // u32 per stage: A 1024 + B 2048 (12KB)
#define G_STAGES 4
#define G_DSMEM  (G_STAGES * G_STFL * 4)     // 48KB

template<int KT, int MODE>
__global__ void __launch_bounds__(128, 3)
gemm_f16_kernel(const float* __restrict__ combW, const int* __restrict__ species) {
    extern __shared__ uint32_t smu[];

    const int p   = blockIdx.x >> 1;
    const int nh  = blockIdx.x & 1;
    const int b64 = blockIdx.y;
    const int m0  = b64 * 64;

    const uint32_t* Ag = (MODE == 0)
        ? g_featP + (size_t)b64 * KT0 * 1024
        : g_h1f   + (size_t)(p * MBLK64 + b64) * (KT1 * 1024);
    const uint32_t* Bg = ((MODE == 0) ? g_W0f + (size_t)p * KT0 * 4096
                                      : g_W1f + (size_t)p * KT1 * 4096) + nh * 2048;

    const int tid  = threadIdx.x;
    const int warp = tid >> 5;
    const int lane = tid & 31;
    const int grp  = lane >> 2;
    const int tig  = lane & 3;
    const int wmB  = (warp & 1) * 2;     // m16-block base (2 per warp)
    const int wnB  = (warp >> 1) * 8;    // n8-block base within 16 (8 per warp)

    float acc[2][8][4];
    #pragma unroll
    for (int mt = 0; mt < 2; mt++)
        #pragma unroll
        for (int nt = 0; nt < 8; nt++)
            #pragma unroll
            for (int i = 0; i < 4; i++) acc[mt][nt][i] = 0.0f;

    const uint32_t sbase = smem_u32(smu);

    // 12KB linear copy per k-tile: 768 x 16B, 6 per thread
    auto load_tile = [&](int kt, int b) {
        const uint4* srcA = (const uint4*)(Ag + (size_t)kt * 1024);
        const uint4* srcB = (const uint4*)(Bg + (size_t)kt * 4096);
        const uint32_t dst0 = sbase + (uint32_t)b * (G_STFL * 4);
        #pragma unroll
        for (int j = 0; j < 6; j++) {
            int c = tid + 128 * j;
            const uint4* src = (c < 256) ? (srcA + c) : (srcB + (c - 256));
            uint32_t dst = dst0 + (uint32_t)c * 16u;
            asm volatile("cp.async.ca.shared.global [%0], [%1], 16;\n"
                         :: "r"(dst), "l"(src));
        }
        asm volatile("cp.async.commit_group;\n");
    };

    load_tile(0, 0);
    load_tile(1, 1);
    load_tile(2, 2);

    for (int kt = 0; kt < KT; kt++) {
        const int b = kt & (G_STAGES - 1);
        if (kt + 2 < KT)      asm volatile("cp.async.wait_group 2;\n");
        else if (kt + 1 < KT) asm volatile("cp.async.wait_group 1;\n");
        else                  asm volatile("cp.async.wait_group 0;\n");
        __syncthreads();
        if (kt + 3 < KT) load_tile(kt + 3, (kt + 3) & (G_STAGES - 1));

        const uint32_t* As = smu + (size_t)b * G_STFL;
        const uint32_t* Bs = As + 1024;

        // kmma-level fragment double buffering (2 kmma of K=16 per tile)
        uint4 a0[2], a1[2];
        uint2 bv[2][8];
        a0[0] = *(const uint4*)(As + ((wmB    ) * 2 + 0) * 128 + lane * 4);
        a1[0] = *(const uint4*)(As + ((wmB + 1) * 2 + 0) * 128 + lane * 4);
        #pragma unroll
        for (int nt = 0; nt < 8; nt++)
            bv[0][nt] = *(const uint2*)(Bs + ((wnB + nt) * 2 + 0) * 64 + lane * 2);

        #pragma unroll
        for (int km = 0; km < 2; km++) {
            if (km == 0) {
                a0[1] = *(const uint4*)(As + ((wmB    ) * 2 + 1) * 128 + lane * 4);
                a1[1] = *(const uint4*)(As + ((wmB + 1) * 2 + 1) * 128 + lane * 4);
                #pragma unroll
                for (int nt = 0; nt < 8; nt++)
                    bv[1][nt] = *(const uint2*)(Bs + ((wnB + nt) * 2 + 1) * 64 + lane * 2);
            }
            const uint32_t* af0 = (const uint32_t*)&a0[km];
            const uint32_t* af1 = (const uint32_t*)&a1[km];
            #pragma unroll
            for (int nt = 0; nt < 8; nt++) {
                const uint32_t* bf = (const uint32_t*)&bv[km][nt];
                mma_f16(acc[0][nt], af0, bf);
                mma_f16(acc[1][nt], af1, bf);
            }
        }
        __syncthreads();
    }

    // ---------------- epilogue ----------------
    #pragma unroll
    for (int mt = 0; mt < 2; mt++) {
        const int b16 = wmB + mt;
        const int r0 = m0 + b16 * 16 + grp;
        const int r1 = r0 + 8;
        float pw0 = 1.0f, pw1 = 1.0f;
        if (MODE == 0) {
            pw0 = (r0 < N_ATOMS) ? combW[p * NSPECIES + species[r0]] : 0.0f;
            pw1 = (r1 < N_ATOMS) ? combW[p * NSPECIES + species[r1]] : 0.0f;
        }
        #pragma unroll
        for (int nt = 0; nt < 8; nt++) {
            const int c = (nh * 16 + wnB + nt) * 8 + tig * 2;   // global hidden col
            float x0 = silu(acc[mt][nt][0] * pw0);
            float x1 = silu(acc[mt][nt][1] * pw0);
            float x2 = silu(acc[mt][nt][2] * pw1);
            float x3 = silu(acc[mt][nt][3] * pw1);
            __half2 v01 = __floats2half2_rn(x0, x1);
            __half2 v23 = __floats2half2_rn(x2, x3);
            if (MODE == 0) {
                // write straight into fragment-major h1 (A of GEMM1)
                const int kt1 = c >> 5, kmma = (c >> 4) & 1, khalf = (c >> 3) & 1;
                uint32_t* base = g_h1f + (size_t)(p * MBLK64 + b64) * (KT1 * 1024)
                               + (((size_t)(kt1 * 4 + b16) * 2 + kmma) * 32 + lane) * 4;
                base[2 * khalf    ] = *(uint32_t*)&v01;
                base[2 * khalf + 1] = *(uint32_t*)&v23;
            } else {
                __half* C = g_h2h + (size_t)p * N_ATOMS * HIDDEN;
                if (r0 < N_ATOMS) *(uint32_t*)&C[(size_t)r0 * HIDDEN + c] = *(uint32_t*)&v01;
                if (r1 < N_ATOMS) *(uint32_t*)&C[(size_t)r1 * HIDDEN + c] = *(uint32_t*)&v23;
            }
        }
    }
}

// ---------------- final dot + segment sum ----------------
__global__ void zero_out_kernel(float* out) {
    if (threadIdx.x < N_STRUCT) out[threadIdx.x] = 0.0f;
}

__global__ void reduce_kernel(const float* __restrict__ W2,
                              const int* __restrict__ sid,
                              float* __restrict__ out) {
    const int a = blockIdx.x;
    const int t = threadIdx.x;
    float v = 0.0f;
    #pragma unroll
    for (int p = 0; p < NPSEUDO; p++)
        v += __half2float(g_h2h[((size_t)p * N_ATOMS + a) * HIDDEN + t]) * W2[p * HIDDEN + t];

    __shared__ float red[8];
    #pragma unroll
    for (int o = 16; o > 0; o >>= 1) v += __shfl_down_sync(0xffffffffu, v, o);
    if ((t & 31) == 0) red[t >> 5] = v;
    __syncthreads();
    if (t < 8) {
        float s = red[t];
        #pragma unroll
        for (int o = 4; o > 0; o >>= 1) s += __shfl_down_sync(0xffu, s, o);
        if (t == 0) atomicAdd(&out[sid[a]], s);
    }
}

// ---------------- launch ----------------
extern "C" void kernel_launch(void* const* d_in, const int* in_sizes, int n_in,
                              void* d_out, int out_size) {
    const float* c0      = (const float*)d_in[0];
    const float* c1      = (const float*)d_in[1];
    const float* c2      = (const float*)d_in[2];
    const float* c3      = (const float*)d_in[3];
    const int*   species = (const int*)d_in[4];
    const int*   sid     = (const int*)d_in[5];
    const float* combW   = (const float*)d_in[6];
    const float* W0      = (const float*)d_in[7];
    const float* W1      = (const float*)d_in[8];
    const float* W2      = (const float*)d_in[9];
    float* out = (float*)d_out;

    static bool attr_set = false;
    if (!attr_set) {
        cudaFuncSetAttribute(gemm_f16_kernel<KT0, 0>,
                             cudaFuncAttributeMaxDynamicSharedMemorySize, G_DSMEM);
        cudaFuncSetAttribute(gemm_f16_kernel<KT1, 1>,
                             cudaFuncAttributeMaxDynamicSharedMemorySize, G_DSMEM);
        attr_set = true;
    }

    {
        dim3 g(NPACK, NPSEUDO);
        convert_w0_kernel<<<g, 256>>>(W0);
    }
    {
        dim3 g(HIDDEN, NPSEUDO);
        convert_w1_kernel<<<g, 256>>>(W1);
    }

    features_kernel<<<APAD, 256>>>(c0, c1, c2, c3);

    {
        dim3 g(NPSEUDO * 2, MBLK64);
        gemm_f16_kernel<KT0, 0><<<g, 128, G_DSMEM>>>(combW, species);
        gemm_f16_kernel<KT1, 1><<<g, 128, G_DSMEM>>>(combW, species);
    }

    zero_out_kernel<<<1, 128>>>(out);
    reduce_kernel<<<N_ATOMS, 256>>>(W2, sid, out);
}